// round 2
// baseline (speedup 1.0000x reference)
#include <cuda_runtime.h>

// Kalman filter: NCV state (4) + 128 static per-sensor biases.
// Exact structure exploited:
//  - obs[0:64] observe p_x, obs[64:128] observe p_y (H reshape is C-order!)
//  - x/y components exactly decoupled
//  - sensor exchangeability -> aggregate 3-state KF (p, v, sum_b) per comp
//    with scalar measurement ybar = p + sum_b/64 + noise(R/64), plus a fully
//    decoupled per-sensor scalar KF on delta_i = b_i - bbar with variance w:
//        w' = w*R/(w+R),  delta_i += (w/alpha)*( (y_i - ybar) - delta_i )
//  - loglik: quad = ai*sum r_tilde^2 + Ib^2/Sv ; logdet = 63 ln(a) + ln(64 Sv)
// Aggregate mean chain runs in fp64 (slow p-vs-bbar mode has 4096-step
// memory); restructured so the per-step fp64 critical path is 2 ops.

#define T_STEPS 4096
#define OBS 128

__device__ float g_sumy[2 * T_STEPS];

__global__ void sumy_kernel(const float4* __restrict__ obs4) {
    int gw   = (blockIdx.x * blockDim.x + threadIdx.x) >> 5;
    int lane = threadIdx.x & 31;
    int nw   = (gridDim.x * blockDim.x) >> 5;
    for (int t = gw; t < T_STEPS; t += nw) {
        float4 v = obs4[t * 32 + lane];
        // lanes 0..15 cover obs 0..63 (x group); lanes 16..31 cover 64..127 (y)
        float s = (v.x + v.y) + (v.z + v.w);
        #pragma unroll
        for (int m = 8; m; m >>= 1)
            s += __shfl_xor_sync(0xffffffffu, s, m);
        if (lane == 0)  g_sumy[2 * t]     = s;   // x-group sum
        if (lane == 16) g_sumy[2 * t + 1] = s;   // y-group sum
    }
}

__global__ void __launch_bounds__(128, 1) kalman_kernel(
    const float* __restrict__ obs,
    const float* __restrict__ lbs,
    const float* __restrict__ lon,
    const float* __restrict__ ltn,
    float* __restrict__ out)
{
    __shared__ float s_sy[2 * T_STEPS];   // 32 KB per-step group sums
    __shared__ float s_red[128];

    const int tid = threadIdx.x;
    for (int i = tid; i < 2 * T_STEPS; i += 128) s_sy[i] = g_sumy[i];
    __syncthreads();

    const float R  = expf(2.0f * lon[0]);   // obs_noise^2
    const float q  = expf(2.0f * ltn[0]);   // trans_noise^2
    const float g0 = expf(2.0f * lbs[0]);   // bias_scale^2
    const float q1 = q, q2 = 0.5f * q, q3 = q * (1.0f / 3.0f);
    const float inv64 = 0.015625f;

    // aggregate covariance per component (identical for x and y)
    float a = 100.0f, c = 100.0f, d = 0.0f;
    float e2 = 0.0f, f2 = 0.0f, g2 = 64.0f * g0;   // cov with / var of sum_b
    float w  = g0;                                  // idiosyncratic bias var
    float ld = 0.0f;                                // logdet accumulator (lg2)

    // fp64 aggregate means (m = predicted p + sum_b/64; V vel; Pp pred pos)
    double m0 = 0.0, V0 = 0.0, Pp0 = 0.0, mV0 = 0.0, PpV0 = 0.0;
    double m1 = 0.0, V1 = 0.0, Pp1 = 0.0, mV1 = 0.0, PpV1 = 0.0;
    double pu0 = 0.0, vu0 = 0.0, pu1 = 0.0, vu1 = 0.0;
    double llq = 0.0;

    // per-thread idiosyncratic bias
    float delta = 0.0f, acc = 0.0f;
    const int comp = (tid >= 64);            // obs 0..63 -> x, 64..127 -> y
    const float* yp = obs + tid;
    float yA = yp[0];
    float yB = yp[OBS];

    for (int t = 0; t < T_STEPS; ++t) {
        int tn = t + 2; if (tn > T_STEPS - 1) tn = T_STEPS - 1;
        float yC  = yp[tn * OBS];
        float sy0 = s_sy[2 * t];
        float sy1 = s_sy[2 * t + 1];

        // ---- aggregate covariance (fp32, data independent) ----
        float cp  = c + q1;
        float dp  = (d + c) + q2;
        float ap  = fmaf(2.0f, d, a) + (c + q3);
        float e2p = e2 + f2;
        float u1  = fmaf(e2p, inv64, ap);      // cov(p, ybar)
        float u2  = fmaf(f2,  inv64, dp);      // cov(v, ybar)
        float u3  = fmaf(g2,  inv64, e2p);     // cov(sum_b, ybar)
        float Sv  = fmaf(u3 + R, inv64, u1);   // var(ybar)
        float iSv = 1.0f / Sv;
        float k1  = u1 * iSv;
        float k2  = u2 * iSv;
        float k3  = u3 * iSv;
        a  = fmaf(-k1, u1, ap);
        d  = fmaf(-k1, u2, dp);
        c  = fmaf(-k2, u2, cp);
        e2 = fmaf(-k1, u3, e2p);
        f2 = fmaf(-k2, u3, f2);
        g2 = fmaf(-k3, u3, g2);
        float alpha = w + R;
        float ia    = 1.0f / alpha;
        float kap   = w * ia;
        w = kap * R;                           // w*R/(w+R), no cancellation
        ld += fmaf(63.0f, __log2f(alpha), __log2f(64.0f * Sv));

        // ---- aggregate means (fp64, critical path = 2 ops/step) ----
        double k1d = (double)k1, k2d = (double)k2;
        double k12 = k1d + k2d;
        double km  = fma((double)k3, 0.015625, k12);
        double yb0 = (double)sy0 * 0.015625;
        double yb1 = (double)sy1 * 0.015625;
        double Ib0 = yb0 - m0;
        double Ib1 = yb1 - m1;
        llq = fma(fma(Ib1, Ib1, Ib0 * Ib0), (double)iSv, llq);
        pu0 = fma(k1d, Ib0, Pp0);  vu0 = fma(k2d, Ib0, V0);
        pu1 = fma(k1d, Ib1, Pp1);  vu1 = fma(k2d, Ib1, V1);
        double mn0  = fma(km,  Ib0, mV0);
        double mn1  = fma(km,  Ib1, mV1);
        double Ppn0 = fma(k12, Ib0, PpV0);
        double Ppn1 = fma(k12, Ib1, PpV1);
        V0 = vu0;  V1 = vu1;
        Pp0 = Ppn0;  Pp1 = Ppn1;
        m0 = mn0;    m1 = mn1;
        mV0  = mn0 + vu0;   mV1  = mn1 + vu1;
        PpV0 = Ppn0 + vu0;  PpV1 = Ppn1 + vu1;

        // ---- per-thread idiosyncratic bias + quad form ----
        float ybar = (comp ? sy1 : sy0) * inv64;
        float rt   = (yA - ybar) - delta;
        delta = fmaf(kap, rt, delta);
        acc   = fmaf(ia, rt * rt, acc);

        yA = yB;
        yB = yC;
    }

    s_red[tid] = acc;
    __syncthreads();

    if (tid == 0) {
        double atot = 0.0;
        for (int i = 0; i < 128; ++i) atot += (double)s_red[i];
        const double LN2    = 0.6931471805599453094;
        const double LOG2PI = 1.8378770664093454836;
        double quad = 0.5 * (atot + llq);
        double logp = -quad - (double)ld * LN2
                      - 64.0 * (double)T_STEPS * LOG2PI;
        out[0] = (float)logp;
        out[1] = (float)pu0;  out[2] = (float)pu1;
        out[3] = (float)vu0;  out[4] = (float)vu1;
        // post_cov = [[a,0,d,0],[0,a,0,d],[d,0,c,0],[0,d,0,c]]
        out[5]  = a;   out[6]  = 0.f; out[7]  = d;   out[8]  = 0.f;
        out[9]  = 0.f; out[10] = a;   out[11] = 0.f; out[12] = d;
        out[13] = d;   out[14] = 0.f; out[15] = c;   out[16] = 0.f;
        out[17] = 0.f; out[18] = d;   out[19] = 0.f; out[20] = c;
    }
}

extern "C" void kernel_launch(void* const* d_in, const int* in_sizes, int n_in,
                              void* d_out, int out_size) {
    const float* obs = (const float*)d_in[0];
    const float* lbs = (const float*)d_in[1];
    const float* lon = (const float*)d_in[2];
    const float* ltn = (const float*)d_in[3];
    float* out = (float*)d_out;
    (void)in_sizes; (void)n_in; (void)out_size;

    sumy_kernel<<<64, 256>>>((const float4*)obs);
    kalman_kernel<<<1, 128>>>(obs, lbs, lon, ltn, out);
}

// round 3
// speedup vs baseline: 19.7567x; 19.7567x over previous
#include <cuda_runtime.h>

// Kalman filter: NCV(4) + 128 static sensor biases, T=4096.
// Exact decomposition (validated in round 2):
//   obs[0:64]->p_x, obs[64:128]->p_y; x/y decoupled; sensor-exchangeable.
//   Aggregate 3-state KF per comp on ybar; idiosyncratic scalar KF per sensor
//   with closed-form variance w_t = g0*R/(R + t*g0).
// This round: all-fp32, warp-specialized pipelines:
//   warp0: data-independent Riccati gain chain -> smem gain ring
//   warp1: mean/loglik chain (lags one 32-step window; named barrier 1)
//   warps2-3: 128 sensor bias chains (2/thread), depth-8 obs prefetch
//   Sum log(alpha_t) telescopes -> computed once at the end.

#define T_STEPS 4096
#define OBS 128
#define WIN 32
#define NWIN (T_STEPS / WIN)

__device__ float g_ybar[2 * T_STEPS];

__global__ void ybar_kernel(const float4* __restrict__ obs4) {
    int gw   = (blockIdx.x * blockDim.x + threadIdx.x) >> 5;
    int lane = threadIdx.x & 31;
    int nw   = (gridDim.x * blockDim.x) >> 5;
    for (int t = gw; t < T_STEPS; t += nw) {
        float4 v = obs4[t * 32 + lane];
        // lanes 0..15: obs 0..63 (x group); lanes 16..31: obs 64..127 (y)
        float s = (v.x + v.y) + (v.z + v.w);
        #pragma unroll
        for (int m = 8; m; m >>= 1)
            s += __shfl_xor_sync(0xffffffffu, s, m);
        s *= 0.015625f;
        if (lane == 0)  g_ybar[2 * t]     = s;
        if (lane == 16) g_ybar[2 * t + 1] = s;
    }
}

__device__ __forceinline__ float frcp(float x) {
    float r;
    asm("rcp.approx.f32 %0, %1;" : "=f"(r) : "f"(x));
    return r;
}

__global__ void __launch_bounds__(256, 1) kalman_kernel(
    const float* __restrict__ obs,
    const float* __restrict__ lbs,
    const float* __restrict__ lon,
    const float* __restrict__ ltn,
    float* __restrict__ out)
{
    __shared__ float  s_yb[2 * T_STEPS];      // 32 KB: ybar per (t, comp)
    __shared__ float4 s_g[2][WIN];            // gains ring (k1,k2,k3,iSv)
    __shared__ float  s_red[64];              // sensor-warp partials
    __shared__ float  s_fin[12];              // cross-warp final scalars

    const int tid  = threadIdx.x;
    const int wid  = tid >> 5;
    const int lane = tid & 31;

    // stage ybar into shared
    {
        const float4* src = (const float4*)g_ybar;
        float4*       dst = (float4*)s_yb;
        #pragma unroll
        for (int i = tid; i < 2 * T_STEPS / 4; i += 256) dst[i] = src[i];
    }

    const float R  = expf(2.0f * lon[0]);
    const float q  = expf(2.0f * ltn[0]);
    const float g0 = expf(2.0f * lbs[0]);
    const float q1 = q, q2 = 0.5f * q, q3 = q * (1.0f / 3.0f);
    const float inv64 = 0.015625f;

    __syncthreads();

    if (wid == 0) {
        // ================= covariance / gain chain =================
        float a = 100.0f, c = 100.0f, d = 0.0f;
        float e2 = 0.0f, f2 = 0.0f, g2 = 64.0f * g0;
        float ldS = 0.0f;
        for (int w = 0; w <= NWIN; ++w) {
            if (w < NWIN) {
                float4* gbuf = s_g[w & 1];
                #pragma unroll 4
                for (int j = 0; j < WIN; ++j) {
                    float cp  = c + q1;
                    float dp  = (d + c) + q2;
                    float ap  = fmaf(2.0f, d, a) + (c + q3);
                    float e2p = e2 + f2;
                    float u1  = fmaf(e2p, inv64, ap);
                    float u2  = fmaf(f2,  inv64, dp);
                    float u3  = fmaf(g2,  inv64, e2p);
                    float Sv  = fmaf(u3 + R, inv64, u1);
                    float iSv = frcp(Sv);
                    float k1  = u1 * iSv;
                    float k2  = u2 * iSv;
                    float k3  = u3 * iSv;
                    a  = fmaf(-k1, u1, ap);
                    d  = fmaf(-k1, u2, dp);
                    c  = fmaf(-k2, u2, cp);
                    e2 = fmaf(-k1, u3, e2p);
                    f2 = fmaf(-k2, u3, f2);
                    g2 = fmaf(-k3, u3, g2);
                    ldS += __log2f(Sv);
                    if (lane == 0) gbuf[j] = make_float4(k1, k2, k3, iSv);
                }
            }
            asm volatile("bar.sync 1, 64;" ::: "memory");
        }
        if (lane == 0) {
            s_fin[0] = ldS; s_fin[1] = a; s_fin[2] = d; s_fin[3] = c;
        }
    } else if (wid == 1) {
        // ================= mean / loglik chain =================
        float m0 = 0.f, V0 = 0.f, Pp0 = 0.f, mV0 = 0.f, PpV0 = 0.f;
        float m1 = 0.f, V1 = 0.f, Pp1 = 0.f, mV1 = 0.f, PpV1 = 0.f;
        float pu0 = 0.f, vu0 = 0.f, pu1 = 0.f, vu1 = 0.f;
        float llq = 0.f;
        for (int w = 0; w <= NWIN; ++w) {
            if (w > 0) {
                const float4* gbuf = s_g[(w - 1) & 1];
                int tbase = (w - 1) * WIN;
                #pragma unroll 4
                for (int j = 0; j < WIN; ++j) {
                    float4 g4  = gbuf[j];
                    float  yb0 = s_yb[2 * (tbase + j)];
                    float  yb1 = s_yb[2 * (tbase + j) + 1];
                    float Ib0 = yb0 - m0;
                    float Ib1 = yb1 - m1;
                    float k12 = g4.x + g4.y;
                    float km  = fmaf(g4.z, inv64, k12);
                    float ss  = fmaf(Ib1, Ib1, Ib0 * Ib0);
                    llq = fmaf(ss, g4.w, llq);
                    pu0 = fmaf(g4.x, Ib0, Pp0);
                    pu1 = fmaf(g4.x, Ib1, Pp1);
                    vu0 = fmaf(g4.y, Ib0, V0);
                    vu1 = fmaf(g4.y, Ib1, V1);
                    float mn0  = fmaf(km,  Ib0, mV0);
                    float mn1  = fmaf(km,  Ib1, mV1);
                    float Ppn0 = fmaf(k12, Ib0, PpV0);
                    float Ppn1 = fmaf(k12, Ib1, PpV1);
                    V0 = vu0;   V1 = vu1;
                    Pp0 = Ppn0; Pp1 = Ppn1;
                    m0 = mn0;   m1 = mn1;
                    mV0  = mn0 + vu0;   mV1  = mn1 + vu1;
                    PpV0 = Ppn0 + vu0;  PpV1 = Ppn1 + vu1;
                }
            }
            asm volatile("bar.sync 1, 64;" ::: "memory");
        }
        if (lane == 0) {
            s_fin[4] = llq;
            s_fin[5] = pu0; s_fin[6] = pu1;
            s_fin[7] = vu0; s_fin[8] = vu1;
        }
    } else if (wid < 4) {
        // ================= sensor bias chains (2 per thread) =================
        const int sid = tid - 64;                 // 0..63
        const float* yp0 = obs + sid;             // comp 0 sensor
        const float* yp1 = obs + sid + 64;        // comp 1 sensor
        float d0 = 0.f, d1 = 0.f, acc0 = 0.f, acc1 = 0.f;
        float y0r[8], y1r[8];
        #pragma unroll
        for (int j = 0; j < 8; ++j) {
            y0r[j] = yp0[j * OBS];
            y1r[j] = yp1[j * OBS];
        }
        const float iR  = frcp(R);
        float tp1  = 1.0f;
        float den0 = R;
        for (int t0 = 0; t0 < T_STEPS; t0 += 8) {
            #pragma unroll
            for (int j = 0; j < 8; ++j) {
                int t = t0 + j;
                float yb0 = s_yb[2 * t];
                float yb1 = s_yb[2 * t + 1];
                float den1 = fmaf(tp1, g0, R);
                float u    = frcp(den1);
                float kap  = g0 * u;
                float ia   = den0 * u * iR;
                den0 = den1;
                tp1 += 1.0f;
                float rt0 = (y0r[j] - yb0) - d0;
                float rt1 = (y1r[j] - yb1) - d1;
                d0 = fmaf(kap, rt0, d0);
                d1 = fmaf(kap, rt1, d1);
                acc0 = fmaf(ia, rt0 * rt0, acc0);
                acc1 = fmaf(ia, rt1 * rt1, acc1);
                int pf = t + 8; if (pf > T_STEPS - 1) pf = T_STEPS - 1;
                y0r[j] = yp0[pf * OBS];
                y1r[j] = yp1[pf * OBS];
            }
        }
        s_red[sid] = acc0 + acc1;
    }
    __syncthreads();

    if (tid == 0) {
        float atot = 0.0f;
        #pragma unroll 8
        for (int i = 0; i < 64; ++i) atot += s_red[i];
        double ldS = (double)s_fin[0];
        double llq = (double)s_fin[4];
        // telescoped sum of log2(alpha_t):
        double ldA = (double)(T_STEPS - 1) * log2((double)R)
                   + log2((double)R + (double)T_STEPS * (double)g0);
        double ld  = 63.0 * ldA + ldS + 6.0 * (double)T_STEPS;
        const double LN2    = 0.6931471805599453094;
        const double LOG2PI = 1.8378770664093454836;
        double quad = 0.5 * ((double)atot + llq);
        double logp = -quad - ld * LN2 - 64.0 * (double)T_STEPS * LOG2PI;
        out[0] = (float)logp;
        out[1] = s_fin[5];  out[2] = s_fin[6];
        out[3] = s_fin[7];  out[4] = s_fin[8];
        float a = s_fin[1], d = s_fin[2], c = s_fin[3];
        out[5]  = a;   out[6]  = 0.f; out[7]  = d;   out[8]  = 0.f;
        out[9]  = 0.f; out[10] = a;   out[11] = 0.f; out[12] = d;
        out[13] = d;   out[14] = 0.f; out[15] = c;   out[16] = 0.f;
        out[17] = 0.f; out[18] = d;   out[19] = 0.f; out[20] = c;
    }
}

extern "C" void kernel_launch(void* const* d_in, const int* in_sizes, int n_in,
                              void* d_out, int out_size) {
    const float* obs = (const float*)d_in[0];
    const float* lbs = (const float*)d_in[1];
    const float* lon = (const float*)d_in[2];
    const float* ltn = (const float*)d_in[3];
    float* out = (float*)d_out;
    (void)in_sizes; (void)n_in; (void)out_size;

    ybar_kernel<<<64, 256>>>((const float4*)obs);
    kalman_kernel<<<1, 256>>>(obs, lbs, lon, ltn, out);
}

// round 4
// speedup vs baseline: 20.2404x; 1.0245x over previous
#include <cuda_runtime.h>

// Kalman: NCV(4) + 128 static sensor biases, T=4096. Exact decomposition
// (validated rounds 2-3): obs[0:64]->p_x, obs[64:128]->p_y; aggregate
// 3-state KF per comp on ybar; per-sensor scalar KF on delta with
// closed-form variance; sum log(alpha) telescopes.
// Round 4: instruction-count rebalance of the warp-specialized pipelines.
//   warp0: rescaled Riccati (bias vars pre-divided by 64) -> gains ring
//   warp1: mean/loglik chain, lagged one 64-step window (named barrier 1);
//          stores iSv for deferred logdet; final pos = Ppn - vu.
//   warps2-3: 128 sensor chains, (kap,ia) from precomputed smem table.

#define T_STEPS 4096
#define OBS 128
#define WIN 64
#define NWIN (T_STEPS / WIN)

__device__ float g_ybar[2 * T_STEPS];

__global__ void ybar_kernel(const float4* __restrict__ obs4) {
    int gw   = (blockIdx.x * blockDim.x + threadIdx.x) >> 5;
    int lane = threadIdx.x & 31;
    int nw   = (gridDim.x * blockDim.x) >> 5;
    for (int t = gw; t < T_STEPS; t += nw) {
        float4 v = obs4[t * 32 + lane];
        // lanes 0..15: obs 0..63 (x group); lanes 16..31: obs 64..127 (y)
        float s = (v.x + v.y) + (v.z + v.w);
        #pragma unroll
        for (int m = 8; m; m >>= 1)
            s += __shfl_xor_sync(0xffffffffu, s, m);
        s *= 0.015625f;
        if (lane == 0)  g_ybar[2 * t]     = s;
        if (lane == 16) g_ybar[2 * t + 1] = s;
    }
}

__device__ __forceinline__ float frcp(float x) {
    float r;
    asm("rcp.approx.f32 %0, %1;" : "=f"(r) : "f"(x));
    return r;
}

// dynamic smem layout (floats):
//   [0)      float2 yb[4096]      8192
//   [8192)   float2 kapia[4096]   8192
//   [16384)  float  isv[4096]     4096
//   [20480)  float4 gring[2*WIN]   512
//   [20992)  float  red[64]
//   [21056)  float  ld[256]
//   [21312)  float  fin[16]
#define SMEM_FLOATS 21328
#define SMEM_BYTES  (SMEM_FLOATS * 4)

__global__ void __launch_bounds__(256, 1) kalman_kernel(
    const float* __restrict__ obs,
    const float* __restrict__ lbs,
    const float* __restrict__ lon,
    const float* __restrict__ ltn,
    float* __restrict__ out)
{
    extern __shared__ float smem[];
    float2* s_yb  = (float2*)smem;
    float2* s_ki  = (float2*)(smem + 8192);
    float*  s_isv = smem + 16384;
    float4* s_g   = (float4*)(smem + 20480);
    float*  s_red = smem + 20992;
    float*  s_ld  = smem + 21056;
    float*  s_fin = smem + 21312;

    const int tid  = threadIdx.x;
    const int wid  = tid >> 5;
    const int lane = tid & 31;

    const float R  = expf(2.0f * lon[0]);
    const float q  = expf(2.0f * ltn[0]);
    const float g0 = expf(2.0f * lbs[0]);
    const float q1 = q, q2 = 0.5f * q, q3 = q * (1.0f / 3.0f);
    const float R64 = R * 0.015625f;
    const float iR  = frcp(R);

    // ---- prologue: stage ybar, build (kap, ia) table ----
    {
        const float4* src = (const float4*)g_ybar;
        float4*       dst = (float4*)s_yb;
        #pragma unroll
        for (int i = tid; i < 2 * T_STEPS / 4; i += 256) dst[i] = src[i];
    }
    for (int t = tid; t < T_STEPS; t += 256) {
        float den0 = fmaf((float)t, g0, R);
        float den1 = den0 + g0;
        float u    = frcp(den1);
        float kap  = g0 * u;
        float ia   = den0 * u * iR;     // 1/alpha_t
        s_ki[t] = make_float2(kap, ia);
    }
    __syncthreads();

    if (wid == 0) {
        // =========== Riccati gain chain (rescaled bias vars) ===========
        // E = e2/64, F = f2/64, G = g2/4096; kB == k3 in this scaling.
        float a = 100.0f, c = 100.0f, d = 0.0f;
        float E = 0.0f, F = 0.0f, G = g0 * 0.015625f;
        for (int w = 0; w <= NWIN; ++w) {
            if (w < NWIN) {
                float4* gb = s_g + (w & 1) * WIN;
                #pragma unroll 8
                for (int j = 0; j < WIN; ++j) {
                    float cp = c + q1;
                    float dc = d + c;
                    float dp = dc + q2;
                    float a2 = fmaf(2.0f, d, a);
                    float cq = c + q3;
                    float ap = a2 + cq;
                    float Ep = E + F;
                    float u1 = ap + Ep;
                    float u2 = dp + F;
                    float u3 = Ep + G;
                    float Sv = (u1 + u3) + R64;
                    float is = frcp(Sv);
                    float k1 = u1 * is;
                    float k2 = u2 * is;
                    float k3 = u3 * is;
                    a = fmaf(-k1, u1, ap);
                    d = fmaf(-k1, u2, dp);
                    c = fmaf(-k2, u2, cp);
                    E = fmaf(-k1, u3, Ep);
                    F = fmaf(-k2, u3, F);
                    G = fmaf(-k3, u3, G);
                    if (lane == 0) gb[j] = make_float4(k1, k2, k3, is);
                }
            }
            asm volatile("bar.sync 1, 64;" ::: "memory");
        }
        if (lane == 0) {
            s_fin[1] = a; s_fin[2] = d; s_fin[3] = c;
        }
    } else if (wid == 1) {
        // =========== mean / loglik chain (lags one window) ===========
        float m0 = 0.f, m1 = 0.f, V0 = 0.f, V1 = 0.f;
        float mV0 = 0.f, mV1 = 0.f, PV0 = 0.f, PV1 = 0.f;
        float Pn0 = 0.f, Pn1 = 0.f, llq = 0.f;
        for (int w = 0; w <= NWIN; ++w) {
            if (w > 0) {
                const float4* gb = s_g + ((w - 1) & 1) * WIN;
                const int tb = (w - 1) * WIN;
                const float2* ybp = s_yb + tb;
                float* isvp = s_isv + tb;
                #pragma unroll 8
                for (int j = 0; j < WIN; ++j) {
                    float4 g4 = gb[j];
                    float2 yb = ybp[j];
                    float k12 = g4.x + g4.y;
                    float km  = k12 + g4.z;
                    float Ib0 = yb.x - m0;
                    float Ib1 = yb.y - m1;
                    float vu0 = fmaf(g4.y, Ib0, V0);
                    float vu1 = fmaf(g4.y, Ib1, V1);
                    float mn0 = fmaf(km, Ib0, mV0);
                    float mn1 = fmaf(km, Ib1, mV1);
                    Pn0 = fmaf(k12, Ib0, PV0);
                    Pn1 = fmaf(k12, Ib1, PV1);
                    mV0 = mn0 + vu0;  mV1 = mn1 + vu1;
                    PV0 = Pn0 + vu0;  PV1 = Pn1 + vu1;
                    m0 = mn0;  m1 = mn1;
                    V0 = vu0;  V1 = vu1;
                    float ss = Ib0 * Ib0;
                    ss = fmaf(Ib1, Ib1, ss);
                    llq = fmaf(ss, g4.w, llq);
                    if (lane == 0) isvp[j] = g4.w;
                }
            }
            asm volatile("bar.sync 1, 64;" ::: "memory");
        }
        if (lane == 0) {
            s_fin[4] = llq;
            s_fin[5] = Pn0 - V0;  s_fin[6] = Pn1 - V1;   // posterior pos
            s_fin[7] = V0;        s_fin[8] = V1;          // posterior vel
        }
    } else if (wid < 4) {
        // =========== sensor bias chains (2 per thread) ===========
        const int sid = tid - 64;                 // 0..63
        const float* yp0 = obs + sid;
        const float* yp1 = obs + sid + 64;
        float d0 = 0.f, d1 = 0.f, acc0 = 0.f, acc1 = 0.f;
        float y0r[8], y1r[8];
        #pragma unroll
        for (int j = 0; j < 8; ++j) {
            y0r[j] = yp0[j * OBS];
            y1r[j] = yp1[j * OBS];
        }
        for (int t0 = 0; t0 < T_STEPS; t0 += 8) {
            #pragma unroll
            for (int j = 0; j < 8; ++j) {
                int t = t0 + j;
                float2 yb = s_yb[t];
                float2 ki = s_ki[t];
                float rt0 = (y0r[j] - yb.x) - d0;
                float rt1 = (y1r[j] - yb.y) - d1;
                d0 = fmaf(ki.x, rt0, d0);
                d1 = fmaf(ki.x, rt1, d1);
                acc0 = fmaf(ki.y, rt0 * rt0, acc0);
                acc1 = fmaf(ki.y, rt1 * rt1, acc1);
                int pf = t + 8; if (pf > T_STEPS - 1) pf = T_STEPS - 1;
                y0r[j] = yp0[pf * OBS];
                y1r[j] = yp1[pf * OBS];
            }
        }
        s_red[sid] = acc0 + acc1;
    }
    __syncthreads();

    // deferred logdet: ldS = sum_t log2(Sv_t) = -sum_t log2(iSv_t)
    {
        float ls = 0.0f;
        for (int t = tid; t < T_STEPS; t += 256)
            ls += __log2f(s_isv[t]);
        s_ld[tid] = ls;
    }
    __syncthreads();

    if (tid == 0) {
        float atot = 0.0f;
        #pragma unroll 8
        for (int i = 0; i < 64; ++i) atot += s_red[i];
        float lsum = 0.0f;
        #pragma unroll 8
        for (int i = 0; i < 256; ++i) lsum += s_ld[i];
        double ldS = -(double)lsum;
        double llq = (double)s_fin[4];
        double ldA = (double)(T_STEPS - 1) * log2((double)R)
                   + log2((double)R + (double)T_STEPS * (double)g0);
        double ld  = 63.0 * ldA + ldS + 6.0 * (double)T_STEPS;
        const double LN2    = 0.6931471805599453094;
        const double LOG2PI = 1.8378770664093454836;
        double quad = 0.5 * ((double)atot + llq);
        double logp = -quad - ld * LN2 - 64.0 * (double)T_STEPS * LOG2PI;
        out[0] = (float)logp;
        out[1] = s_fin[5];  out[2] = s_fin[6];
        out[3] = s_fin[7];  out[4] = s_fin[8];
        float a = s_fin[1], d = s_fin[2], c = s_fin[3];
        out[5]  = a;   out[6]  = 0.f; out[7]  = d;   out[8]  = 0.f;
        out[9]  = 0.f; out[10] = a;   out[11] = 0.f; out[12] = d;
        out[13] = d;   out[14] = 0.f; out[15] = c;   out[16] = 0.f;
        out[17] = 0.f; out[18] = d;   out[19] = 0.f; out[20] = c;
    }
}

extern "C" void kernel_launch(void* const* d_in, const int* in_sizes, int n_in,
                              void* d_out, int out_size) {
    const float* obs = (const float*)d_in[0];
    const float* lbs = (const float*)d_in[1];
    const float* lon = (const float*)d_in[2];
    const float* ltn = (const float*)d_in[3];
    float* out = (float*)d_out;
    (void)in_sizes; (void)n_in; (void)out_size;

    static bool attr_set = false;
    if (!attr_set) {
        cudaFuncSetAttribute(kalman_kernel,
                             cudaFuncAttributeMaxDynamicSharedMemorySize,
                             SMEM_BYTES);
        attr_set = true;
    }
    ybar_kernel<<<64, 256>>>((const float4*)obs);
    kalman_kernel<<<1, 256, SMEM_BYTES>>>(obs, lbs, lon, ltn, out);
}

// round 5
// speedup vs baseline: 25.3157x; 1.2508x over previous
#include <cuda_runtime.h>

// Kalman: NCV(4) + 128 static sensor biases, T=4096. Exact decomposition
// (validated rounds 2-4). Round 5: f32x2-packed warp-specialized pipelines
// + Newton reciprocal (hybrid: exact rcp in first window) + W-trick, to
// lower both the fma-pipe issue floor and the loop-carried RAW chain of
// the Riccati warp.

#define T_STEPS 4096
#define OBS 128
#define WIN 64
#define NWIN (T_STEPS / WIN)

typedef unsigned long long u64;

__device__ float g_ybar[2 * T_STEPS];

__global__ void ybar_kernel(const float4* __restrict__ obs4) {
    int gw   = (blockIdx.x * blockDim.x + threadIdx.x) >> 5;
    int lane = threadIdx.x & 31;
    int nw   = (gridDim.x * blockDim.x) >> 5;
    for (int t = gw; t < T_STEPS; t += nw) {
        float4 v = obs4[t * 32 + lane];
        float s = (v.x + v.y) + (v.z + v.w);
        #pragma unroll
        for (int m = 8; m; m >>= 1)
            s += __shfl_xor_sync(0xffffffffu, s, m);
        s *= 0.015625f;
        if (lane == 0)  g_ybar[2 * t]     = s;
        if (lane == 16) g_ybar[2 * t + 1] = s;
    }
}

__device__ __forceinline__ float frcp(float x) {
    float r;
    asm("rcp.approx.f32 %0, %1;" : "=f"(r) : "f"(x));
    return r;
}
__device__ __forceinline__ u64 pk2(float lo, float hi) {
    u64 d;
    asm("mov.b64 %0, {%1, %2};" : "=l"(d)
        : "r"(__float_as_uint(lo)), "r"(__float_as_uint(hi)));
    return d;
}
__device__ __forceinline__ void unpk2(u64 v, float& lo, float& hi) {
    unsigned a, b;
    asm("mov.b64 {%0, %1}, %2;" : "=r"(a), "=r"(b) : "l"(v));
    lo = __uint_as_float(a); hi = __uint_as_float(b);
}
__device__ __forceinline__ u64 fma2(u64 a, u64 b, u64 c) {
    u64 d;
    asm("fma.rn.f32x2 %0, %1, %2, %3;" : "=l"(d) : "l"(a), "l"(b), "l"(c));
    return d;
}
__device__ __forceinline__ u64 add2(u64 a, u64 b) {
    u64 d;
    asm("add.rn.f32x2 %0, %1, %2;" : "=l"(d) : "l"(a), "l"(b));
    return d;
}
__device__ __forceinline__ u64 mul2(u64 a, u64 b) {
    u64 d;
    asm("mul.rn.f32x2 %0, %1, %2;" : "=l"(d) : "l"(a), "l"(b));
    return d;
}
__device__ __forceinline__ float fneg(float x) {
    return __uint_as_float(__float_as_uint(x) ^ 0x80000000u);
}

// One Riccati step. FIRST: exact rcp (transient window). Else Newton from
// carried nis (negated reciprocal of Sv).
template <bool FIRST>
__device__ __forceinline__ void ricc_step(
    float& a, float& d, float& c, float& E, float& F, float& G, float& nis,
    float q1s, float q2s, float q3s, float R64s,
    bool do_store, ulonglong2* gout)
{
    float dc = d + c;
    float s1 = fmaf(2.0f, d, a);
    float cq = c + q3s;
    float ap = s1 + cq;
    float dp = dc + q2s;
    float cp = c + q1s;
    float Ep = E + F;
    float GR = G + R64s;
    float W  = fmaf(2.0f, Ep, GR);
    float Sv = ap + W;
    if (FIRST) {
        nis = fneg(frcp(Sv));
    } else {
        float tt = fmaf(Sv, nis, 2.0f);
        nis = nis * tt;
    }
    float u1 = ap + Ep;
    float u2 = dp + F;
    float u3 = Ep + G;
    float nk3 = u3 * nis;
    u64 u12  = pk2(u1, u2);
    u64 niss = pk2(nis, nis);
    u64 nk12 = mul2(u12, niss);          // (-k1, -k2)
    float nk1, nk2;
    unpk2(nk12, nk1, nk2);
    u64 AD = fma2(u12, pk2(nk1, nk1), pk2(ap, dp));   // (a', d')
    u64 EF = fma2(nk12, pk2(u3, u3), pk2(Ep, F));     // (E', F')
    u64 CG = fma2(pk2(nk2, nk3), pk2(u2, u3), pk2(cp, G)); // (c', G')
    unpk2(AD, a, d);
    unpk2(EF, E, F);
    unpk2(CG, c, G);
    if (do_store) {
        ulonglong2 e;
        e.x = nk12;
        e.y = pk2(nk3, nis);
        *gout = e;
    }
}

// dynamic smem layout (floats):
//   [0)      float2 yb[4096]       8192
//   [8192)   float2 kapia[4096]    8192
//   [16384)  float  isv[4096]      4096
//   [20480)  ulonglong2 g[2*WIN]    512 floats (2KB)
//   [20992)  float  red[64]
//   [21056)  float  ld[256]
//   [21312)  float  fin[16]
#define SMEM_FLOATS 21328
#define SMEM_BYTES  (SMEM_FLOATS * 4)

__global__ void __launch_bounds__(256, 1) kalman_kernel(
    const float* __restrict__ obs,
    const float* __restrict__ lbs,
    const float* __restrict__ lon,
    const float* __restrict__ ltn,
    float* __restrict__ out)
{
    extern __shared__ float smem[];
    float2*     s_yb  = (float2*)smem;
    float2*     s_ki  = (float2*)(smem + 8192);
    float*      s_isv = smem + 16384;
    ulonglong2* s_g   = (ulonglong2*)(smem + 20480);
    float*      s_red = smem + 20992;
    float*      s_ld  = smem + 21056;
    float*      s_fin = smem + 21312;

    const int tid  = threadIdx.x;
    const int wid  = tid >> 5;
    const int lane = tid & 31;

    const float R  = expf(2.0f * lon[0]);
    const float q  = expf(2.0f * ltn[0]);
    const float g0 = expf(2.0f * lbs[0]);
    const float q1 = q, q2 = 0.5f * q, q3 = q * (1.0f / 3.0f);
    const float R64 = R * 0.015625f;
    const float iR  = frcp(R);

    // ---- prologue: stage ybar, build (kap, ia) table ----
    {
        const float4* src = (const float4*)g_ybar;
        float4*       dst = (float4*)s_yb;
        #pragma unroll
        for (int i = tid; i < 2 * T_STEPS / 4; i += 256) dst[i] = src[i];
    }
    for (int t = tid; t < T_STEPS; t += 256) {
        float den0 = fmaf((float)t, g0, R);
        float den1 = den0 + g0;
        float u    = frcp(den1);
        float kap  = g0 * u;
        float ia   = den0 * u * iR;     // 1/alpha_t
        s_ki[t] = make_float2(kap, ia);
    }
    __syncthreads();

    if (wid == 0) {
        // =========== Riccati gain chain ===========
        float a = 100.0f, c = 100.0f, d = 0.0f;
        float E = 0.0f, F = 0.0f, G = g0 * 0.015625f;
        float nis = -1.0f;
        const bool st = (lane == 0);
        for (int w = 0; w <= NWIN; ++w) {
            if (w == 0) {
                ulonglong2* gb = s_g;
                #pragma unroll 8
                for (int j = 0; j < WIN; ++j)
                    ricc_step<true>(a, d, c, E, F, G, nis,
                                    q1, q2, q3, R64, st, gb + j);
            } else if (w < NWIN) {
                ulonglong2* gb = s_g + (w & 1) * WIN;
                #pragma unroll 8
                for (int j = 0; j < WIN; ++j)
                    ricc_step<false>(a, d, c, E, F, G, nis,
                                     q1, q2, q3, R64, st, gb + j);
            }
            asm volatile("bar.sync 1, 64;" ::: "memory");
        }
        if (lane == 0) {
            s_fin[1] = a; s_fin[2] = d; s_fin[3] = c;
        }
    } else if (wid == 1) {
        // =========== mean / loglik chain (lags one window) ===========
        const u64 NEG1 = pk2(-1.0f, -1.0f);
        u64 m2 = 0, V2 = 0, mV2 = 0, PV2 = 0, Pn2 = 0, llq2 = 0;
        for (int w = 0; w <= NWIN; ++w) {
            if (w > 0) {
                const ulonglong2* gb = s_g + ((w - 1) & 1) * WIN;
                const int tb = (w - 1) * WIN;
                const u64* ybp = (const u64*)(s_yb + tb);
                float* isvp = s_isv + tb;
                #pragma unroll 8
                for (int j = 0; j < WIN; ++j) {
                    ulonglong2 e = gb[j];
                    float nk1, nk2, nk3, nis;
                    unpk2(e.x, nk1, nk2);
                    unpk2(e.y, nk3, nis);
                    float k12n = nk1 + nk2;
                    float kmn  = k12n + nk3;
                    float k2v  = fneg(nk2);
                    float k12  = fneg(k12n);
                    float km   = fneg(kmn);
                    float is   = fneg(nis);
                    u64 yb2  = ybp[j];
                    u64 Ib   = fma2(m2, NEG1, yb2);
                    u64 vu   = fma2(pk2(k2v, k2v), Ib, V2);
                    u64 mn   = fma2(pk2(km, km),  Ib, mV2);
                    Pn2      = fma2(pk2(k12, k12), Ib, PV2);
                    mV2 = add2(mn, vu);
                    PV2 = add2(Pn2, vu);
                    m2 = mn;  V2 = vu;
                    u64 ss = mul2(Ib, Ib);
                    llq2 = fma2(ss, pk2(is, is), llq2);
                    if (lane == 0) isvp[j] = is;
                }
            }
            asm volatile("bar.sync 1, 64;" ::: "memory");
        }
        if (lane == 0) {
            float l0, l1, P0, P1, V0, V1;
            unpk2(llq2, l0, l1);
            unpk2(Pn2, P0, P1);
            unpk2(V2, V0, V1);
            s_fin[4] = l0 + l1;
            s_fin[5] = P0 - V0;  s_fin[6] = P1 - V1;   // posterior pos
            s_fin[7] = V0;       s_fin[8] = V1;         // posterior vel
        }
    } else if (wid < 4) {
        // =========== sensor bias chains (2 per thread, packed) ===========
        const int sid = tid - 64;                 // 0..63
        const float* yp0 = obs + sid;
        const float* yp1 = obs + sid + 64;
        const u64 NEG1 = pk2(-1.0f, -1.0f);
        u64 d2 = 0, acc2 = 0;
        const u64* ybp = (const u64*)s_yb;
        float y0r[8], y1r[8];
        #pragma unroll
        for (int j = 0; j < 8; ++j) {
            y0r[j] = yp0[j * OBS];
            y1r[j] = yp1[j * OBS];
        }
        for (int t0 = 0; t0 < T_STEPS; t0 += 8) {
            #pragma unroll
            for (int j = 0; j < 8; ++j) {
                int t = t0 + j;
                u64 yb2 = ybp[t];
                float2 ki = s_ki[t];
                u64 y2  = pk2(y0r[j], y1r[j]);
                u64 s   = add2(yb2, d2);           // yb + d
                u64 rt2 = fma2(s, NEG1, y2);       // y - yb - d
                d2   = fma2(pk2(ki.x, ki.x), rt2, d2);
                u64 sq = mul2(rt2, rt2);
                acc2 = fma2(sq, pk2(ki.y, ki.y), acc2);
                int pf = t + 8; if (pf > T_STEPS - 1) pf = T_STEPS - 1;
                y0r[j] = yp0[pf * OBS];
                y1r[j] = yp1[pf * OBS];
            }
        }
        float a0, a1;
        unpk2(acc2, a0, a1);
        s_red[sid] = a0 + a1;
    }
    __syncthreads();

    // deferred logdet: ldS = sum_t log2(Sv_t) = -sum_t log2(iSv_t)
    {
        float ls = 0.0f;
        for (int t = tid; t < T_STEPS; t += 256)
            ls += __log2f(s_isv[t]);
        s_ld[tid] = ls;
    }
    __syncthreads();

    if (tid == 0) {
        float atot = 0.0f;
        #pragma unroll 8
        for (int i = 0; i < 64; ++i) atot += s_red[i];
        float lsum = 0.0f;
        #pragma unroll 8
        for (int i = 0; i < 256; ++i) lsum += s_ld[i];
        double ldS = -(double)lsum;
        double llq = (double)s_fin[4];
        double ldA = (double)(T_STEPS - 1) * log2((double)R)
                   + log2((double)R + (double)T_STEPS * (double)g0);
        double ld  = 63.0 * ldA + ldS + 6.0 * (double)T_STEPS;
        const double LN2    = 0.6931471805599453094;
        const double LOG2PI = 1.8378770664093454836;
        double quad = 0.5 * ((double)atot + llq);
        double logp = -quad - ld * LN2 - 64.0 * (double)T_STEPS * LOG2PI;
        out[0] = (float)logp;
        out[1] = s_fin[5];  out[2] = s_fin[6];
        out[3] = s_fin[7];  out[4] = s_fin[8];
        float a = s_fin[1], d = s_fin[2], c = s_fin[3];
        out[5]  = a;   out[6]  = 0.f; out[7]  = d;   out[8]  = 0.f;
        out[9]  = 0.f; out[10] = a;   out[11] = 0.f; out[12] = d;
        out[13] = d;   out[14] = 0.f; out[15] = c;   out[16] = 0.f;
        out[17] = 0.f; out[18] = d;   out[19] = 0.f; out[20] = c;
    }
}

extern "C" void kernel_launch(void* const* d_in, const int* in_sizes, int n_in,
                              void* d_out, int out_size) {
    const float* obs = (const float*)d_in[0];
    const float* lbs = (const float*)d_in[1];
    const float* lon = (const float*)d_in[2];
    const float* ltn = (const float*)d_in[3];
    float* out = (float*)d_out;
    (void)in_sizes; (void)n_in; (void)out_size;

    static bool attr_set = false;
    if (!attr_set) {
        cudaFuncSetAttribute(kalman_kernel,
                             cudaFuncAttributeMaxDynamicSharedMemorySize,
                             SMEM_BYTES);
        attr_set = true;
    }
    ybar_kernel<<<64, 256>>>((const float4*)obs);
    kalman_kernel<<<1, 256, SMEM_BYTES>>>(obs, lbs, lon, ltn, out);
}